// round 3
// baseline (speedup 1.0000x reference)
#include <cuda_runtime.h>
#include <math.h>
#include <stddef.h>

// ---------------------------------------------------------------------------
// Transformer encoder, 12 blocks, shared weights.
// B=4, N=512, D=768, F=3072, H=12, hd=64.  All fp32.
// ---------------------------------------------------------------------------

#define BATCH   4
#define SEQ     512
#define DMODEL  768
#define FFN     3072
#define HEADS   12
#define HDIM    64
#define MROWS   (BATCH * SEQ)        // 2048
#define NBLK    12
#define LN_EPS  1e-5f

// Scratch (static device globals -- no allocations anywhere)
__device__ float g_ln[MROWS * DMODEL];                  //  6.3 MB
__device__ float g_q [MROWS * DMODEL];                  //  6.3 MB
__device__ float g_k [MROWS * DMODEL];                  //  6.3 MB
__device__ float g_v [MROWS * DMODEL];                  //  6.3 MB
__device__ float g_h1[MROWS * FFN];                     // 25.2 MB

// ---------------------------------------------------------------------------
// Block-wide reductions (256 threads = 8 warps)
// ---------------------------------------------------------------------------
__device__ __forceinline__ float blk_sum(float v) {
    __shared__ float red[8];
    int t = threadIdx.x;
#pragma unroll
    for (int o = 16; o; o >>= 1) v += __shfl_xor_sync(0xffffffffu, v, o);
    if ((t & 31) == 0) red[t >> 5] = v;
    __syncthreads();
    if (t < 32) {
        float w = (t < 8) ? red[t] : 0.f;
#pragma unroll
        for (int o = 4; o; o >>= 1) w += __shfl_xor_sync(0xffffffffu, w, o);
        if (t == 0) red[0] = w;
    }
    __syncthreads();
    float r = red[0];
    __syncthreads();
    return r;
}

// ---------------------------------------------------------------------------
// LayerNorm: one block (256 thr) per row of 768
// ---------------------------------------------------------------------------
__global__ void __launch_bounds__(256) ln_kernel(const float* __restrict__ x,
                                                 const float* __restrict__ g,
                                                 const float* __restrict__ be,
                                                 float* __restrict__ y) {
    int row = blockIdx.x;
    int t   = threadIdx.x;
    const float* xr = x + (size_t)row * DMODEL;
    float v0 = xr[t], v1 = xr[t + 256], v2 = xr[t + 512];
    float mean = blk_sum(v0 + v1 + v2) * (1.0f / DMODEL);
    float d0 = v0 - mean, d1 = v1 - mean, d2 = v2 - mean;
    float var = blk_sum(d0 * d0 + d1 * d1 + d2 * d2) * (1.0f / DMODEL);
    float rs = rsqrtf(var + LN_EPS);
    float* yr = y + (size_t)row * DMODEL;
    yr[t]       = d0 * rs * g[t]       + be[t];
    yr[t + 256] = d1 * rs * g[t + 256] + be[t + 256];
    yr[t + 512] = d2 * rs * g[t + 512] + be[t + 512];
}

// ---------------------------------------------------------------------------
// Tiled GEMM: C[M x Ncols] = A[M x Kdim] * B[Kdim x Ncols] (+epilogue)
// Tile 128 x TN x 16, 256 threads, 8 x (TN/16) per thread.
// Register-staged double-buffered smem, float4 global loads/stores,
// one __syncthreads per K-iter.
// EPI bit0: +bias   bit1: exact GELU   bit2: C += (residual, in place)
// ---------------------------------------------------------------------------
template <int TN, int EPI>
__global__ void __launch_bounds__(256) gemm_kernel(const float* __restrict__ A,
                                                   const float* __restrict__ B,
                                                   const float* __restrict__ bias,
                                                   float* __restrict__ C,
                                                   int Ncols, int Kdim) {
    constexpr int TM = 128, TK = 16;
    constexpr int WN  = TN / 16;                 // cols per thread (4 or 8)
    constexpr int BF4 = (TK * TN / 4) / 256;     // B float4 per thread (1 or 2)
    constexpr int AP  = TM + 4;                  // As row pad

    __shared__ float As[2][TK][AP];
    __shared__ float Bs[2][TK][TN];

    const int tid  = threadIdx.x;
    const int tx   = tid & 15;
    const int ty   = tid >> 4;
    const int row0 = blockIdx.y * TM;
    const int col0 = blockIdx.x * TN;

    const int aM = tid >> 2;                 // 0..63 ; second frag at aM+64
    const int aK = (tid & 3) * 4;            // 0,4,8,12
    constexpr int bDiv = TN / 4;
    int bK[BF4], bN[BF4];
#pragma unroll
    for (int r = 0; r < BF4; r++) {
        int i = tid + 256 * r;
        bK[r] = i / bDiv;
        bN[r] = (i % bDiv) * 4;
    }

    const float* aBase0 = A + (size_t)(row0 + aM)      * Kdim + aK;
    const float* aBase1 = A + (size_t)(row0 + aM + 64) * Kdim + aK;

    float acc[8][WN];
#pragma unroll
    for (int i = 0; i < 8; i++)
#pragma unroll
        for (int j = 0; j < WN; j++) acc[i][j] = 0.f;

    const int KT = Kdim / TK;
    float4 af0, af1, bf[BF4];

    // ---- prologue ----
    af0 = *(const float4*)(aBase0);
    af1 = *(const float4*)(aBase1);
#pragma unroll
    for (int r = 0; r < BF4; r++)
        bf[r] = *(const float4*)&B[(size_t)bK[r] * Ncols + col0 + bN[r]];

    As[0][aK + 0][aM]      = af0.x; As[0][aK + 1][aM]      = af0.y;
    As[0][aK + 2][aM]      = af0.z; As[0][aK + 3][aM]      = af0.w;
    As[0][aK + 0][aM + 64] = af1.x; As[0][aK + 1][aM + 64] = af1.y;
    As[0][aK + 2][aM + 64] = af1.z; As[0][aK + 3][aM + 64] = af1.w;
#pragma unroll
    for (int r = 0; r < BF4; r++)
        *(float4*)&Bs[0][bK[r]][bN[r]] = bf[r];
    __syncthreads();

    for (int kt = 0; kt < KT; kt++) {
        const int cur = kt & 1;
        const bool has_next = (kt + 1 < KT);

        if (has_next) {
            const int k0 = (kt + 1) * TK;
            af0 = *(const float4*)(aBase0 + k0);
            af1 = *(const float4*)(aBase1 + k0);
#pragma unroll
            for (int r = 0; r < BF4; r++)
                bf[r] = *(const float4*)&B[(size_t)(k0 + bK[r]) * Ncols + col0 + bN[r]];
        }

#pragma unroll
        for (int k = 0; k < TK; k++) {
            float a[8], bb[WN];
#pragma unroll
            for (int i = 0; i < 8; i++) a[i]  = As[cur][k][ty * 8 + i];
#pragma unroll
            for (int j = 0; j < WN; j++) bb[j] = Bs[cur][k][tx * WN + j];
#pragma unroll
            for (int i = 0; i < 8; i++)
#pragma unroll
                for (int j = 0; j < WN; j++) acc[i][j] = fmaf(a[i], bb[j], acc[i][j]);
        }

        if (has_next) {
            const int nxt = cur ^ 1;
            As[nxt][aK + 0][aM]      = af0.x; As[nxt][aK + 1][aM]      = af0.y;
            As[nxt][aK + 2][aM]      = af0.z; As[nxt][aK + 3][aM]      = af0.w;
            As[nxt][aK + 0][aM + 64] = af1.x; As[nxt][aK + 1][aM + 64] = af1.y;
            As[nxt][aK + 2][aM + 64] = af1.z; As[nxt][aK + 3][aM + 64] = af1.w;
#pragma unroll
            for (int r = 0; r < BF4; r++)
                *(float4*)&Bs[nxt][bK[r]][bN[r]] = bf[r];
        }
        __syncthreads();
    }

    // ---- vectorized epilogue ----
#pragma unroll
    for (int i = 0; i < 8; i++) {
        int r = row0 + ty * 8 + i;
        float* crow = C + (size_t)r * Ncols + col0 + tx * WN;
        const float* brow = bias + col0 + tx * WN;
#pragma unroll
        for (int j4 = 0; j4 < WN / 4; j4++) {
            float4 v4;
            v4.x = acc[i][j4 * 4 + 0]; v4.y = acc[i][j4 * 4 + 1];
            v4.z = acc[i][j4 * 4 + 2]; v4.w = acc[i][j4 * 4 + 3];
            if (EPI & 1) {
                float4 b4 = *(const float4*)(brow + j4 * 4);
                v4.x += b4.x; v4.y += b4.y; v4.z += b4.z; v4.w += b4.w;
            }
            if (EPI & 2) {
                const float c = 0.70710678118654752f;
                v4.x = 0.5f * v4.x * (1.0f + erff(v4.x * c));
                v4.y = 0.5f * v4.y * (1.0f + erff(v4.y * c));
                v4.z = 0.5f * v4.z * (1.0f + erff(v4.z * c));
                v4.w = 0.5f * v4.w * (1.0f + erff(v4.w * c));
            }
            if (EPI & 4) {
                float4 o4 = *(const float4*)(crow + j4 * 4);
                v4.x += o4.x; v4.y += o4.y; v4.z += o4.z; v4.w += o4.w;
            }
            *(float4*)(crow + j4 * 4) = v4;
        }
    }
}

// ---------------------------------------------------------------------------
// Fused flash-style attention: one block per (bh, 64-query tile).
// S = Q K^T / 8, online softmax, O += P V, residual add into x.
// 256 threads; thread (ty,tx) owns S/O rows ty*4+i, cols tx*4+j.
// Row statistics reduced over the 16-thread tx-group via shfl (lanes differ
// only in bits 0..3, so xor-shuffles of 1,2,4,8 stay inside the group).
// ---------------------------------------------------------------------------
__global__ void __launch_bounds__(256) attn_kernel(const float* __restrict__ q,
                                                   const float* __restrict__ k,
                                                   const float* __restrict__ v,
                                                   float* __restrict__ x) {
    __shared__ float Qs[64][68];   // [d][query]
    __shared__ float Ks[64][68];   // [d][key]
    __shared__ float Vs[64][68];   // [key][d]
    __shared__ float Ps[64][68];   // [key][query]

    const int bh = blockIdx.y;
    const int b = bh / HEADS, h = bh % HEADS;
    const int q0 = blockIdx.x * 64;
    const float* qb = q + (size_t)b * SEQ * DMODEL + h * HDIM;
    const float* kb = k + (size_t)b * SEQ * DMODEL + h * HDIM;
    const float* vb = v + (size_t)b * SEQ * DMODEL + h * HDIM;

    const int tid = threadIdx.x;
    const int tx = tid & 15, ty = tid >> 4;

    // load Q tile (float4 global reads)
    for (int i = tid; i < 64 * 16; i += 256) {
        int m = i >> 4, c = (i & 15) * 4;
        float4 t = *(const float4*)&qb[(size_t)(q0 + m) * DMODEL + c];
        Qs[c + 0][m] = t.x; Qs[c + 1][m] = t.y;
        Qs[c + 2][m] = t.z; Qs[c + 3][m] = t.w;
    }

    float O[4][4] = {};
    float mrow[4], lrow[4];
#pragma unroll
    for (int i = 0; i < 4; i++) { mrow[i] = -1e30f; lrow[i] = 0.f; }

    for (int j0 = 0; j0 < SEQ; j0 += 64) {
        __syncthreads();   // previous iter's P*V reads done before K/V overwrite
        for (int i = tid; i < 64 * 16; i += 256) {
            int m = i >> 4, c = (i & 15) * 4;
            float4 tk = *(const float4*)&kb[(size_t)(j0 + m) * DMODEL + c];
            Ks[c + 0][m] = tk.x; Ks[c + 1][m] = tk.y;
            Ks[c + 2][m] = tk.z; Ks[c + 3][m] = tk.w;
            float4 tv = *(const float4*)&vb[(size_t)(j0 + m) * DMODEL + c];
            Vs[m][c + 0] = tv.x; Vs[m][c + 1] = tv.y;
            Vs[m][c + 2] = tv.z; Vs[m][c + 3] = tv.w;
        }
        __syncthreads();

        // S = Q K^T
        float S[4][4] = {};
#pragma unroll 8
        for (int kk = 0; kk < 64; kk++) {
            float a[4], bb[4];
#pragma unroll
            for (int i = 0; i < 4; i++) a[i]  = Qs[kk][ty * 4 + i];
#pragma unroll
            for (int j = 0; j < 4; j++) bb[j] = Ks[kk][tx * 4 + j];
#pragma unroll
            for (int i = 0; i < 4; i++)
#pragma unroll
                for (int j = 0; j < 4; j++) S[i][j] = fmaf(a[i], bb[j], S[i][j]);
        }

        // online softmax over this 64-key slab
        float scale[4], rsum[4];
#pragma unroll
        for (int i = 0; i < 4; i++) {
            float rmax = -1e30f;
#pragma unroll
            for (int j = 0; j < 4; j++) {
                S[i][j] *= 0.125f;
                rmax = fmaxf(rmax, S[i][j]);
            }
#pragma unroll
            for (int o = 8; o; o >>= 1)
                rmax = fmaxf(rmax, __shfl_xor_sync(0xffffffffu, rmax, o));
            float mnew = fmaxf(mrow[i], rmax);
            scale[i] = __expf(mrow[i] - mnew);
            mrow[i] = mnew;
            float rs = 0.f;
#pragma unroll
            for (int j = 0; j < 4; j++) {
                float p = __expf(S[i][j] - mnew);
                S[i][j] = p;
                rs += p;
            }
#pragma unroll
            for (int o = 8; o; o >>= 1)
                rs += __shfl_xor_sync(0xffffffffu, rs, o);
            rsum[i] = rs;
        }
#pragma unroll
        for (int i = 0; i < 4; i++) {
            lrow[i] = lrow[i] * scale[i] + rsum[i];
#pragma unroll
            for (int j = 0; j < 4; j++) {
                Ps[tx * 4 + j][ty * 4 + i] = S[i][j];
                O[i][j] *= scale[i];
            }
        }
        __syncthreads();

        // O += P V
#pragma unroll 8
        for (int kk = 0; kk < 64; kk++) {
            float a[4], bb[4];
#pragma unroll
            for (int i = 0; i < 4; i++) a[i]  = Ps[kk][ty * 4 + i];
#pragma unroll
            for (int j = 0; j < 4; j++) bb[j] = Vs[kk][tx * 4 + j];
#pragma unroll
            for (int i = 0; i < 4; i++)
#pragma unroll
                for (int j = 0; j < 4; j++) O[i][j] = fmaf(a[i], bb[j], O[i][j]);
        }
    }

    // normalize + residual add (float4 RMW)
#pragma unroll
    for (int i = 0; i < 4; i++) {
        float inv = 1.0f / lrow[i];
        float* xr = x + (size_t)(b * SEQ + q0 + ty * 4 + i) * DMODEL + h * HDIM + tx * 4;
        float4 o4 = *(const float4*)xr;
        o4.x += O[i][0] * inv; o4.y += O[i][1] * inv;
        o4.z += O[i][2] * inv; o4.w += O[i][3] * inv;
        *(float4*)xr = o4;
    }
}

// ---------------------------------------------------------------------------
// Launch
// ---------------------------------------------------------------------------
extern "C" void kernel_launch(void* const* d_in, const int* in_sizes, int n_in,
                              void* d_out, int out_size) {
    const float* x  = (const float*)d_in[0];
    const float* Wq = (const float*)d_in[1];
    const float* bq = (const float*)d_in[2];
    const float* Wk = (const float*)d_in[3];
    const float* bk = (const float*)d_in[4];
    const float* Wv = (const float*)d_in[5];
    const float* bv = (const float*)d_in[6];
    const float* g1 = (const float*)d_in[7];
    const float* be1= (const float*)d_in[8];
    const float* g2 = (const float*)d_in[9];
    const float* be2= (const float*)d_in[10];
    const float* W0 = (const float*)d_in[11];
    const float* b0 = (const float*)d_in[12];
    const float* W1 = (const float*)d_in[13];
    const float* b1 = (const float*)d_in[14];
    float* out = (float*)d_out;

    float *ln, *q, *k, *v, *h1;
    cudaGetSymbolAddress((void**)&ln, g_ln);
    cudaGetSymbolAddress((void**)&q,  g_q);
    cudaGetSymbolAddress((void**)&k,  g_k);
    cudaGetSymbolAddress((void**)&v,  g_v);
    cudaGetSymbolAddress((void**)&h1, g_h1);

    // residual stream lives in d_out; re-init every call for replay determinism
    cudaMemcpyAsync(out, x, sizeof(float) * MROWS * DMODEL, cudaMemcpyDeviceToDevice);

    dim3 gQKV(DMODEL / 64, MROWS / 128);   // (12, 16)
    dim3 gFF1(FFN / 128,  MROWS / 128);    // (24, 16)
    dim3 gFF2(DMODEL / 64, MROWS / 128);   // (12, 16)

    for (int blk = 0; blk < NBLK; blk++) {
        // --- attention sub-block ---
        ln_kernel<<<MROWS, 256>>>(out, g1, be1, ln);
        gemm_kernel<64, 1><<<gQKV, 256>>>(ln, Wq, bq, q, DMODEL, DMODEL);
        gemm_kernel<64, 1><<<gQKV, 256>>>(ln, Wk, bk, k, DMODEL, DMODEL);
        gemm_kernel<64, 1><<<gQKV, 256>>>(ln, Wv, bv, v, DMODEL, DMODEL);
        attn_kernel<<<dim3(SEQ / 64, BATCH * HEADS), 256>>>(q, k, v, out); // out += attn

        // --- MLP sub-block ---
        ln_kernel<<<MROWS, 256>>>(out, g2, be2, ln);
        gemm_kernel<128, 3><<<gFF1, 256>>>(ln, W0, b0, h1, FFN, DMODEL);     // bias+gelu
        gemm_kernel<64, 5><<<gFF2, 256>>>(h1, W1, b1, out, DMODEL, FFN);     // bias+residual
    }
}

// round 6
// speedup vs baseline: 1.6158x; 1.6158x over previous
#include <cuda_runtime.h>
#include <cuda_bf16.h>
#include <math.h>
#include <stdint.h>
#include <stddef.h>

// ---------------------------------------------------------------------------
// Transformer encoder, 12 blocks, shared weights.
// B=4, N=512, D=768, F=3072, H=12, hd=64.
// GEMMs: warp-level mma.sync bf16 (HMMA) with bf16x2 split precision.
// Attention/LN: SIMT fp32 (flash-style fused attention).
// NOTE: tcgen05 is NOT usable here -- harness PTX targets sm_103 (no 'a').
// ---------------------------------------------------------------------------

#define BATCH   4
#define SEQ     512
#define DMODEL  768
#define QKVD    2304
#define FFN     3072
#define HEADS   12
#define HDIM    64
#define MROWS   2048
#define NBLK    12
#define LN_EPS  1e-5f

// Scratch (static device globals -- no allocations anywhere)
__device__ float g_ln  [(size_t)MROWS * DMODEL];   //  6.3 MB
__device__ float g_qkv [(size_t)MROWS * QKVD];     // 18.9 MB
__device__ float g_h1  [(size_t)MROWS * FFN];      // 25.2 MB
__device__ float g_wqkv[(size_t)DMODEL * QKVD];    //  7.1 MB
__device__ float g_bqkv[QKVD];

// ---------------------------------------------------------------------------
// helpers
// ---------------------------------------------------------------------------
__device__ __forceinline__ uint32_t smem_u32(const void* p) {
    uint32_t a;
    asm("{ .reg .u64 t; cvta.to.shared.u64 t, %1; cvt.u32.u64 %0, t; }" : "=r"(a) : "l"(p));
    return a;
}

// split a,b into bf16 hi/lo packed pairs (low 16 bits = first element)
__device__ __forceinline__ void split2(float a, float b, uint32_t& h, uint32_t& l) {
    __nv_bfloat16 ha = __float2bfloat16_rn(a);
    __nv_bfloat16 hb = __float2bfloat16_rn(b);
    float ra = a - __bfloat162float(ha);
    float rb = b - __bfloat162float(hb);
    __nv_bfloat16 la = __float2bfloat16_rn(ra);
    __nv_bfloat16 lb = __float2bfloat16_rn(rb);
    h = ((uint32_t)__bfloat16_as_ushort(hb) << 16) | __bfloat16_as_ushort(ha);
    l = ((uint32_t)__bfloat16_as_ushort(lb) << 16) | __bfloat16_as_ushort(la);
}

__device__ __forceinline__ void sts64(uint32_t a, uint32_t x, uint32_t y) {
    asm volatile("st.shared.v2.b32 [%0], {%1,%2};" :: "r"(a), "r"(x), "r"(y) : "memory");
}
__device__ __forceinline__ void ldmA(uint32_t* r, uint32_t addr) {
    asm volatile("ldmatrix.sync.aligned.m8n8.x4.shared.b16 {%0,%1,%2,%3}, [%4];"
        : "=r"(r[0]), "=r"(r[1]), "=r"(r[2]), "=r"(r[3]) : "r"(addr));
}
__device__ __forceinline__ void ldmBT(uint32_t* r, uint32_t addr) {
    asm volatile("ldmatrix.sync.aligned.m8n8.x4.trans.shared.b16 {%0,%1,%2,%3}, [%4];"
        : "=r"(r[0]), "=r"(r[1]), "=r"(r[2]), "=r"(r[3]) : "r"(addr));
}
__device__ __forceinline__ void mma_bf16(float* c, const uint32_t* a, const uint32_t* b) {
    asm volatile("mma.sync.aligned.m16n8k16.row.col.f32.bf16.bf16.f32 "
        "{%0,%1,%2,%3}, {%4,%5,%6,%7}, {%8,%9}, {%0,%1,%2,%3};"
        : "+f"(c[0]), "+f"(c[1]), "+f"(c[2]), "+f"(c[3])
        : "r"(a[0]), "r"(a[1]), "r"(a[2]), "r"(a[3]), "r"(b[0]), "r"(b[1]));
}

// ---------------------------------------------------------------------------
// HMMA GEMM: C[M x Ncols] = A[M x Kdim] * B[Kdim x Ncols] (+epilogue)
// CTA tile 128x128, 8 warps (2x4), warp tile 64x32, K staged 32 per buffer.
// bf16x2 split precision: D = Ah*Bh + Ah*Bl + Al*Bh.
// smem layout (bytes, dynamic):
//   AH [2][128][80B]   @ 0       (rows 32 bf16 + 8 pad = 80B, 16-mult)
//   AL [2][128][80B]   @ 20480
//   BH [2][32][272B]   @ 40960   (rows 128 bf16 + 8 pad = 272B, 16-mult)
//   BL [2][32][272B]   @ 58368      total 75776
// EPI bit0: +bias   bit1: exact GELU   bit2: C += (residual)
// ---------------------------------------------------------------------------
template <int EPI>
__global__ void __launch_bounds__(256) hmma_gemm(const float* __restrict__ A,
                                                 const float* __restrict__ B,
                                                 const float* __restrict__ bias,
                                                 float* __restrict__ C,
                                                 int Ncols, int Kdim) {
    extern __shared__ char smem[];
    const uint32_t sb  = smem_u32(smem);
    const uint32_t sAH = sb, sAL = sb + 20480, sBH = sb + 40960, sBL = sb + 58368;

    const int tid = threadIdx.x, lane = tid & 31, wid = tid >> 5;
    const int wm = wid & 1, wn = wid >> 1;               // warp grid 2 x 4
    const int row0 = blockIdx.y * 128, col0 = blockIdx.x * 128;

    // global-load mapping
    const int arow = tid >> 3, acol4 = tid & 7;          // A: 32 rows/pass x 8 f4
    const int bkrow = tid & 31, bcol4 = tid >> 5;        // B: 32 k-rows x 8 f4/pass

    // ldmatrix per-lane address offsets
    const uint32_t a_off = (uint32_t)((wm * 64 + (lane & 15)) * 80 + (lane >> 4) * 16);
    const uint32_t b_off = (uint32_t)((lane & 15) * 272 + (wn * 32 + (lane >> 4) * 8) * 2);

    float acc[4][4][4];
#pragma unroll
    for (int i = 0; i < 4; i++)
#pragma unroll
        for (int j = 0; j < 4; j++)
#pragma unroll
            for (int q = 0; q < 4; q++) acc[i][j][q] = 0.f;

    const int KT = Kdim / 32;
    uint32_t sa_h[8], sa_l[8], sb_h[8], sb_l[8];

    const float* Abase = A + (size_t)row0 * Kdim + acol4 * 4;
    const float* Bbase = B + (size_t)bkrow * Ncols + col0;

    // ---- prologue: load + store stage 0 into buf 0 ----
#pragma unroll
    for (int p = 0; p < 4; p++) {
        float4 t = *(const float4*)(Abase + (size_t)(arow + p * 32) * Kdim);
        split2(t.x, t.y, sa_h[2 * p], sa_l[2 * p]);
        split2(t.z, t.w, sa_h[2 * p + 1], sa_l[2 * p + 1]);
        float4 u = *(const float4*)(Bbase + (bcol4 + p * 8) * 4);
        split2(u.x, u.y, sb_h[2 * p], sb_l[2 * p]);
        split2(u.z, u.w, sb_h[2 * p + 1], sb_l[2 * p + 1]);
    }
#pragma unroll
    for (int p = 0; p < 4; p++) {
        uint32_t ao = (uint32_t)((arow + p * 32) * 80 + acol4 * 8);
        sts64(sAH + ao, sa_h[2 * p], sa_h[2 * p + 1]);
        sts64(sAL + ao, sa_l[2 * p], sa_l[2 * p + 1]);
        uint32_t bo = (uint32_t)(bkrow * 272 + (bcol4 + p * 8) * 8);
        sts64(sBH + bo, sb_h[2 * p], sb_h[2 * p + 1]);
        sts64(sBL + bo, sb_l[2 * p], sb_l[2 * p + 1]);
    }
    __syncthreads();

    for (int st = 0; st < KT; st++) {
        const int buf = st & 1;
        const bool nxt = (st + 1 < KT);

        if (nxt) {
            const int kb = (st + 1) * 32;
#pragma unroll
            for (int p = 0; p < 4; p++) {
                float4 t = *(const float4*)(Abase + (size_t)(arow + p * 32) * Kdim + kb);
                split2(t.x, t.y, sa_h[2 * p], sa_l[2 * p]);
                split2(t.z, t.w, sa_h[2 * p + 1], sa_l[2 * p + 1]);
                float4 u = *(const float4*)(Bbase + (size_t)kb * Ncols + (bcol4 + p * 8) * 4);
                split2(u.x, u.y, sb_h[2 * p], sb_l[2 * p]);
                split2(u.z, u.w, sb_h[2 * p + 1], sb_l[2 * p + 1]);
            }
        }

        const uint32_t aAH = sAH + buf * 10240, aAL = sAL + buf * 10240;
        const uint32_t aBH = sBH + buf * 8704,  aBL = sBL + buf * 8704;
#pragma unroll
        for (int ks = 0; ks < 2; ks++) {
            const uint32_t bko = (uint32_t)(ks * 16 * 272);
            const uint32_t ako = (uint32_t)(ks * 32);
            uint32_t bh[8], bl[8];
            ldmBT(bh,     aBH + bko + b_off);
            ldmBT(bh + 4, aBH + bko + b_off + 32);
            ldmBT(bl,     aBL + bko + b_off);
            ldmBT(bl + 4, aBL + bko + b_off + 32);
#pragma unroll
            for (int mi = 0; mi < 4; mi++) {
                uint32_t ah[4], al[4];
                ldmA(ah, aAH + a_off + ako + mi * 16 * 80);
                ldmA(al, aAL + a_off + ako + mi * 16 * 80);
#pragma unroll
                for (int ni = 0; ni < 4; ni++) {
                    mma_bf16(acc[mi][ni], ah, bh + ni * 2);
                    mma_bf16(acc[mi][ni], ah, bl + ni * 2);
                    mma_bf16(acc[mi][ni], al, bh + ni * 2);
                }
            }
        }

        if (nxt) {
            const int nb = buf ^ 1;
            const uint32_t nAH = sAH + nb * 10240, nAL = sAL + nb * 10240;
            const uint32_t nBH = sBH + nb * 8704,  nBL = sBL + nb * 8704;
#pragma unroll
            for (int p = 0; p < 4; p++) {
                uint32_t ao = (uint32_t)((arow + p * 32) * 80 + acol4 * 8);
                sts64(nAH + ao, sa_h[2 * p], sa_h[2 * p + 1]);
                sts64(nAL + ao, sa_l[2 * p], sa_l[2 * p + 1]);
                uint32_t bo = (uint32_t)(bkrow * 272 + (bcol4 + p * 8) * 8);
                sts64(nBH + bo, sb_h[2 * p], sb_h[2 * p + 1]);
                sts64(nBL + bo, sb_l[2 * p], sb_l[2 * p + 1]);
            }
        }
        __syncthreads();
    }

    // ---- epilogue (registers -> global, float2) ----
#pragma unroll
    for (int mi = 0; mi < 4; mi++) {
        const int rbase = row0 + wm * 64 + mi * 16 + (lane >> 2);
#pragma unroll
        for (int ni = 0; ni < 4; ni++) {
            const int c = col0 + wn * 32 + ni * 8 + (lane & 3) * 2;
#pragma unroll
            for (int half = 0; half < 2; half++) {
                const int r = rbase + half * 8;
                float v0 = acc[mi][ni][2 * half + 0];
                float v1 = acc[mi][ni][2 * half + 1];
                if (EPI & 1) {
                    float2 b2 = *(const float2*)&bias[c];
                    v0 += b2.x; v1 += b2.y;
                }
                if (EPI & 2) {
                    const float cst = 0.70710678118654752f;
                    v0 = 0.5f * v0 * (1.0f + erff(v0 * cst));
                    v1 = 0.5f * v1 * (1.0f + erff(v1 * cst));
                }
                float* p = &C[(size_t)r * Ncols + c];
                if (EPI & 4) {
                    float2 o = *(const float2*)p;
                    v0 += o.x; v1 += o.y;
                }
                float2 w; w.x = v0; w.y = v1;
                *(float2*)p = w;
            }
        }
    }
}

// ---------------------------------------------------------------------------
// Concat Wq|Wk|Wv -> g_wqkv [768 x 2304], biases -> g_bqkv
// ---------------------------------------------------------------------------
__global__ void __launch_bounds__(256) concat_qkv(const float* __restrict__ Wq,
                                                  const float* __restrict__ Wk,
                                                  const float* __restrict__ Wv,
                                                  const float* __restrict__ bq,
                                                  const float* __restrict__ bk,
                                                  const float* __restrict__ bv) {
    int idx = blockIdx.x * 256 + threadIdx.x;           // 768*2304 total
    int k = idx / QKVD, n = idx % QKVD;
    const float* src = (n < 768) ? Wq : (n < 1536) ? Wk : Wv;
    int nn = (n < 768) ? n : (n < 1536) ? n - 768 : n - 1536;
    g_wqkv[idx] = src[k * 768 + nn];
    if (idx < QKVD)
        g_bqkv[idx] = (idx < 768) ? bq[idx] : (idx < 1536) ? bk[idx - 768] : bv[idx - 1536];
}

// ---------------------------------------------------------------------------
// Block reduction + LayerNorm
// ---------------------------------------------------------------------------
__device__ __forceinline__ float blk_sum(float v) {
    __shared__ float red[8];
    int t = threadIdx.x;
#pragma unroll
    for (int o = 16; o; o >>= 1) v += __shfl_xor_sync(0xffffffffu, v, o);
    if ((t & 31) == 0) red[t >> 5] = v;
    __syncthreads();
    if (t < 32) {
        float w = (t < 8) ? red[t] : 0.f;
#pragma unroll
        for (int o = 4; o; o >>= 1) w += __shfl_xor_sync(0xffffffffu, w, o);
        if (t == 0) red[0] = w;
    }
    __syncthreads();
    float r = red[0];
    __syncthreads();
    return r;
}

__global__ void __launch_bounds__(256) ln_kernel(const float* __restrict__ x,
                                                 const float* __restrict__ g,
                                                 const float* __restrict__ be,
                                                 float* __restrict__ y) {
    int row = blockIdx.x;
    int t   = threadIdx.x;
    const float* xr = x + (size_t)row * DMODEL;
    float v0 = xr[t], v1 = xr[t + 256], v2 = xr[t + 512];
    float mean = blk_sum(v0 + v1 + v2) * (1.0f / DMODEL);
    float d0 = v0 - mean, d1 = v1 - mean, d2 = v2 - mean;
    float var = blk_sum(d0 * d0 + d1 * d1 + d2 * d2) * (1.0f / DMODEL);
    float rs = rsqrtf(var + LN_EPS);
    float* yr = y + (size_t)row * DMODEL;
    yr[t]       = d0 * rs * g[t]       + be[t];
    yr[t + 256] = d1 * rs * g[t + 256] + be[t + 256];
    yr[t + 512] = d2 * rs * g[t + 512] + be[t + 512];
}

// ---------------------------------------------------------------------------
// Fused flash-style attention (qkv packed, row stride QKVD)
// ---------------------------------------------------------------------------
__global__ void __launch_bounds__(256) attn_kernel(const float* __restrict__ qkv,
                                                   float* __restrict__ x) {
    __shared__ float Qs[64][68];
    __shared__ float Ks[64][68];
    __shared__ float Vs[64][68];
    __shared__ float Ps[64][68];

    const int bh = blockIdx.y;
    const int b = bh / HEADS, h = bh % HEADS;
    const int q0 = blockIdx.x * 64;
    const float* qb = qkv + (size_t)b * SEQ * QKVD + h * HDIM;
    const float* kb = qb + 768;
    const float* vb = qb + 1536;

    const int tid = threadIdx.x;
    const int tx = tid & 15, ty = tid >> 4;

    for (int i = tid; i < 64 * 16; i += 256) {
        int m = i >> 4, c = (i & 15) * 4;
        float4 t = *(const float4*)&qb[(size_t)(q0 + m) * QKVD + c];
        Qs[c + 0][m] = t.x; Qs[c + 1][m] = t.y;
        Qs[c + 2][m] = t.z; Qs[c + 3][m] = t.w;
    }

    float O[4][4] = {};
    float mrow[4], lrow[4];
#pragma unroll
    for (int i = 0; i < 4; i++) { mrow[i] = -1e30f; lrow[i] = 0.f; }

    for (int j0 = 0; j0 < SEQ; j0 += 64) {
        __syncthreads();
        for (int i = tid; i < 64 * 16; i += 256) {
            int m = i >> 4, c = (i & 15) * 4;
            float4 tk = *(const float4*)&kb[(size_t)(j0 + m) * QKVD + c];
            Ks[c + 0][m] = tk.x; Ks[c + 1][m] = tk.y;
            Ks[c + 2][m] = tk.z; Ks[c + 3][m] = tk.w;
            float4 tv = *(const float4*)&vb[(size_t)(j0 + m) * QKVD + c];
            Vs[m][c + 0] = tv.x; Vs[m][c + 1] = tv.y;
            Vs[m][c + 2] = tv.z; Vs[m][c + 3] = tv.w;
        }
        __syncthreads();

        float S[4][4] = {};
#pragma unroll 8
        for (int kk = 0; kk < 64; kk++) {
            float a[4], bb[4];
#pragma unroll
            for (int i = 0; i < 4; i++) a[i]  = Qs[kk][ty * 4 + i];
#pragma unroll
            for (int j = 0; j < 4; j++) bb[j] = Ks[kk][tx * 4 + j];
#pragma unroll
            for (int i = 0; i < 4; i++)
#pragma unroll
                for (int j = 0; j < 4; j++) S[i][j] = fmaf(a[i], bb[j], S[i][j]);
        }

        float scale[4], rsum[4];
#pragma unroll
        for (int i = 0; i < 4; i++) {
            float rmax = -1e30f;
#pragma unroll
            for (int j = 0; j < 4; j++) {
                S[i][j] *= 0.125f;
                rmax = fmaxf(rmax, S[i][j]);
            }
#pragma unroll
            for (int o = 8; o; o >>= 1)
                rmax = fmaxf(rmax, __shfl_xor_sync(0xffffffffu, rmax, o));
            float mnew = fmaxf(mrow[i], rmax);
            scale[i] = __expf(mrow[i] - mnew);
            mrow[i] = mnew;
            float rs = 0.f;
#pragma unroll
            for (int j = 0; j < 4; j++) {
                float p = __expf(S[i][j] - mnew);
                S[i][j] = p;
                rs += p;
            }
#pragma unroll
            for (int o = 8; o; o >>= 1)
                rs += __shfl_xor_sync(0xffffffffu, rs, o);
            rsum[i] = rs;
        }
#pragma unroll
        for (int i = 0; i < 4; i++) {
            lrow[i] = lrow[i] * scale[i] + rsum[i];
#pragma unroll
            for (int j = 0; j < 4; j++) {
                Ps[tx * 4 + j][ty * 4 + i] = S[i][j];
                O[i][j] *= scale[i];
            }
        }
        __syncthreads();

#pragma unroll 8
        for (int kk = 0; kk < 64; kk++) {
            float a[4], bb[4];
#pragma unroll
            for (int i = 0; i < 4; i++) a[i]  = Ps[kk][ty * 4 + i];
#pragma unroll
            for (int j = 0; j < 4; j++) bb[j] = Vs[kk][tx * 4 + j];
#pragma unroll
            for (int i = 0; i < 4; i++)
#pragma unroll
                for (int j = 0; j < 4; j++) O[i][j] = fmaf(a[i], bb[j], O[i][j]);
        }
    }

#pragma unroll
    for (int i = 0; i < 4; i++) {
        float inv = 1.0f / lrow[i];
        float* xr = x + (size_t)(b * SEQ + q0 + ty * 4 + i) * DMODEL + h * HDIM + tx * 4;
        float4 o4 = *(const float4*)xr;
        o4.x += O[i][0] * inv; o4.y += O[i][1] * inv;
        o4.z += O[i][2] * inv; o4.w += O[i][3] * inv;
        *(float4*)xr = o4;
    }
}

// ---------------------------------------------------------------------------
// Launch
// ---------------------------------------------------------------------------
extern "C" void kernel_launch(void* const* d_in, const int* in_sizes, int n_in,
                              void* d_out, int out_size) {
    const float* x  = (const float*)d_in[0];
    const float* Wq = (const float*)d_in[1];
    const float* bq = (const float*)d_in[2];
    const float* Wk = (const float*)d_in[3];
    const float* bk = (const float*)d_in[4];
    const float* Wv = (const float*)d_in[5];
    const float* bv = (const float*)d_in[6];
    const float* g1 = (const float*)d_in[7];
    const float* be1= (const float*)d_in[8];
    const float* g2 = (const float*)d_in[9];
    const float* be2= (const float*)d_in[10];
    const float* W0 = (const float*)d_in[11];
    const float* b0 = (const float*)d_in[12];
    const float* W1 = (const float*)d_in[13];
    const float* b1 = (const float*)d_in[14];
    float* out = (float*)d_out;

    float *ln, *qkv, *h1, *wqkv, *bqkv;
    cudaGetSymbolAddress((void**)&ln,   g_ln);
    cudaGetSymbolAddress((void**)&qkv,  g_qkv);
    cudaGetSymbolAddress((void**)&h1,   g_h1);
    cudaGetSymbolAddress((void**)&wqkv, g_wqkv);
    cudaGetSymbolAddress((void**)&bqkv, g_bqkv);

    const int SMB = 75776;
    cudaFuncSetAttribute(hmma_gemm<1>, cudaFuncAttributeMaxDynamicSharedMemorySize, SMB);
    cudaFuncSetAttribute(hmma_gemm<3>, cudaFuncAttributeMaxDynamicSharedMemorySize, SMB);
    cudaFuncSetAttribute(hmma_gemm<5>, cudaFuncAttributeMaxDynamicSharedMemorySize, SMB);

    // residual stream lives in d_out; re-init every call for replay determinism
    cudaMemcpyAsync(out, x, sizeof(float) * (size_t)MROWS * DMODEL, cudaMemcpyDeviceToDevice);
    concat_qkv<<<(DMODEL * QKVD) / 256, 256>>>(Wq, Wk, Wv, bq, bk, bv);

    for (int blk = 0; blk < NBLK; blk++) {
        // --- attention sub-block ---
        ln_kernel<<<MROWS, 256>>>(out, g1, be1, ln);
        hmma_gemm<1><<<dim3(QKVD / 128, MROWS / 128), 256, SMB>>>(
            ln, wqkv, bqkv, qkv, QKVD, DMODEL);
        attn_kernel<<<dim3(SEQ / 64, BATCH * HEADS), 256>>>(qkv, out);   // out += attn

        // --- MLP sub-block ---
        ln_kernel<<<MROWS, 256>>>(out, g2, be2, ln);
        hmma_gemm<3><<<dim3(FFN / 128, MROWS / 128), 256, SMB>>>(
            ln, W0, b0, h1, FFN, DMODEL);                                 // bias+gelu
        hmma_gemm<5><<<dim3(DMODEL / 128, MROWS / 128), 256, SMB>>>(
            h1, W1, b1, out, DMODEL, FFN);                                // bias+residual
    }
}

// round 12
// speedup vs baseline: 2.3406x; 1.4486x over previous
#include <cuda_runtime.h>
#include <cuda_bf16.h>
#include <math.h>
#include <stdint.h>
#include <stddef.h>

// ---------------------------------------------------------------------------
// Transformer encoder, 12 blocks, shared weights.
// B=4, N=512, D=768, F=3072, H=12, hd=64.
// GEMMs: mma.sync bf16 (HMMA), bf16x2 split precision, operands PRE-SPLIT
// outside the mainloop (weights once per call; activations at producer).
// Attention/LN: SIMT fp32 (flash-style fused attention).
// tcgen05 unusable: harness PTX targets sm_103 (no 'a').
// ---------------------------------------------------------------------------

#define BATCH   4
#define SEQ     512
#define DMODEL  768
#define QKVD    2304
#define FFN     3072
#define HEADS   12
#define HDIM    64
#define MROWS   2048
#define NBLK    12
#define LN_EPS  1e-5f

typedef __nv_bfloat16 bf16;

// Scratch (static device globals -- no allocations anywhere)
__device__ bf16  g_lnh [(size_t)MROWS * DMODEL];
__device__ bf16  g_lnl [(size_t)MROWS * DMODEL];
__device__ bf16  g_h1h [(size_t)MROWS * FFN];
__device__ bf16  g_h1l [(size_t)MROWS * FFN];
__device__ bf16  g_wqkvh[(size_t)DMODEL * QKVD];
__device__ bf16  g_wqkvl[(size_t)DMODEL * QKVD];
__device__ bf16  g_w0h [(size_t)DMODEL * FFN];
__device__ bf16  g_w0l [(size_t)DMODEL * FFN];
__device__ bf16  g_w1h [(size_t)FFN * DMODEL];
__device__ bf16  g_w1l [(size_t)FFN * DMODEL];
__device__ float g_qkv [(size_t)MROWS * QKVD];
__device__ float g_bqkv[QKVD];

// ---------------------------------------------------------------------------
// helpers
// ---------------------------------------------------------------------------
__device__ __forceinline__ uint32_t smem_u32(const void* p) {
    uint32_t a;
    asm("{ .reg .u64 t; cvta.to.shared.u64 t, %1; cvt.u32.u64 %0, t; }" : "=r"(a) : "l"(p));
    return a;
}
// split a,b into packed bf16x2 hi/lo (low 16 bits = first element)
__device__ __forceinline__ void split2(float a, float b, uint32_t& h, uint32_t& l) {
    __nv_bfloat16 ha = __float2bfloat16_rn(a);
    __nv_bfloat16 hb = __float2bfloat16_rn(b);
    __nv_bfloat16 la = __float2bfloat16_rn(a - __bfloat162float(ha));
    __nv_bfloat16 lb = __float2bfloat16_rn(b - __bfloat162float(hb));
    h = ((uint32_t)__bfloat16_as_ushort(hb) << 16) | __bfloat16_as_ushort(ha);
    l = ((uint32_t)__bfloat16_as_ushort(lb) << 16) | __bfloat16_as_ushort(la);
}
__device__ __forceinline__ void split1(float a, bf16& h, bf16& l) {
    h = __float2bfloat16_rn(a);
    l = __float2bfloat16_rn(a - __bfloat162float(h));
}
__device__ __forceinline__ void sts128(uint32_t a, uint4 v) {
    asm volatile("st.shared.v4.b32 [%0], {%1,%2,%3,%4};"
        :: "r"(a), "r"(v.x), "r"(v.y), "r"(v.z), "r"(v.w) : "memory");
}
__device__ __forceinline__ void ldmA(uint32_t* r, uint32_t addr) {
    asm volatile("ldmatrix.sync.aligned.m8n8.x4.shared.b16 {%0,%1,%2,%3}, [%4];"
        : "=r"(r[0]), "=r"(r[1]), "=r"(r[2]), "=r"(r[3]) : "r"(addr));
}
__device__ __forceinline__ void ldmBT(uint32_t* r, uint32_t addr) {
    asm volatile("ldmatrix.sync.aligned.m8n8.x4.trans.shared.b16 {%0,%1,%2,%3}, [%4];"
        : "=r"(r[0]), "=r"(r[1]), "=r"(r[2]), "=r"(r[3]) : "r"(addr));
}
__device__ __forceinline__ void mma_bf16(float* c, const uint32_t* a, const uint32_t* b) {
    asm volatile("mma.sync.aligned.m16n8k16.row.col.f32.bf16.bf16.f32 "
        "{%0,%1,%2,%3}, {%4,%5,%6,%7}, {%8,%9}, {%0,%1,%2,%3};"
        : "+f"(c[0]), "+f"(c[1]), "+f"(c[2]), "+f"(c[3])
        : "r"(a[0]), "r"(a[1]), "r"(a[2]), "r"(a[3]), "r"(b[0]), "r"(b[1]));
}

// ---------------------------------------------------------------------------
// HMMA GEMM, pre-split operands:
//   C = (Ah+Al)(Bh+Bl) ~= Ah*Bh + Ah*Bl + Al*Bh
// CTA 128x128, 8 warps (2x4), warp tile 64x32, K staged 32.
// smem: AH[2][128][80B]@0  AL@20480  BH[2][32][272B]@40960  BL@58368 (75776 B)
// EPI bit0:+bias  bit1:GELU  bit2:C+=(residual,fp32)  bit3:split bf16 out
// ---------------------------------------------------------------------------
template <int EPI>
__global__ void __launch_bounds__(256) hmma_gemm(const bf16* __restrict__ Ah,
                                                 const bf16* __restrict__ Al,
                                                 const bf16* __restrict__ Bh,
                                                 const bf16* __restrict__ Bl,
                                                 const float* __restrict__ bias,
                                                 float* __restrict__ C,
                                                 bf16* __restrict__ Ch,
                                                 bf16* __restrict__ Cl,
                                                 int Ncols, int Kdim) {
    extern __shared__ char smem[];
    const uint32_t sb  = smem_u32(smem);
    const uint32_t sAH = sb, sAL = sb + 20480, sBH = sb + 40960, sBL = sb + 58368;

    const int tid = threadIdx.x, lane = tid & 31, wid = tid >> 5;
    const int wm = wid & 1, wn = wid >> 1;               // warp grid 2 x 4
    const int row0 = blockIdx.y * 128, col0 = blockIdx.x * 128;

    // global-load mapping: A 128 rows x 32 bf16 (64B); 2 thr/row, 32B each
    const int arow = tid >> 1, aseg = tid & 1;
    // B: 32 k-rows x 128 bf16 (256B); 8 thr/row, 32B each
    const int bkrow = tid >> 3, bseg = tid & 7;

    const bf16* ArH = Ah + (size_t)(row0 + arow) * Kdim + aseg * 16;
    const bf16* ArL = Al + (size_t)(row0 + arow) * Kdim + aseg * 16;
    const bf16* BrH = Bh + (size_t)bkrow * Ncols + col0 + bseg * 16;
    const bf16* BrL = Bl + (size_t)bkrow * Ncols + col0 + bseg * 16;
    const uint32_t a_sts = (uint32_t)(arow * 80 + aseg * 32);
    const uint32_t b_sts = (uint32_t)(bkrow * 272 + bseg * 32);

    // ldmatrix per-lane address offsets
    const uint32_t a_off = (uint32_t)((wm * 64 + (lane & 15)) * 80 + (lane >> 4) * 16);
    const uint32_t b_off = (uint32_t)((lane & 15) * 272 + (wn * 32 + (lane >> 4) * 8) * 2);

    float acc[4][4][4];
#pragma unroll
    for (int i = 0; i < 4; i++)
#pragma unroll
        for (int j = 0; j < 4; j++)
#pragma unroll
            for (int q = 0; q < 4; q++) acc[i][j][q] = 0.f;

    const int KT = Kdim / 32;
    uint4 rah0, rah1, ral0, ral1, rbh0, rbh1, rbl0, rbl1;

    // ---- prologue: stage 0 -> buf 0 ----
    rah0 = *(const uint4*)(ArH);     rah1 = *(const uint4*)(ArH + 8);
    ral0 = *(const uint4*)(ArL);     ral1 = *(const uint4*)(ArL + 8);
    rbh0 = *(const uint4*)(BrH);     rbh1 = *(const uint4*)(BrH + 8);
    rbl0 = *(const uint4*)(BrL);     rbl1 = *(const uint4*)(BrL + 8);
    sts128(sAH + a_sts, rah0); sts128(sAH + a_sts + 16, rah1);
    sts128(sAL + a_sts, ral0); sts128(sAL + a_sts + 16, ral1);
    sts128(sBH + b_sts, rbh0); sts128(sBH + b_sts + 16, rbh1);
    sts128(sBL + b_sts, rbl0); sts128(sBL + b_sts + 16, rbl1);
    __syncthreads();

    for (int st = 0; st < KT; st++) {
        const int buf = st & 1;
        const bool nxt = (st + 1 < KT);

        if (nxt) {
            const int kb = (st + 1) * 32;
            const size_t bkb = (size_t)kb * Ncols;
            rah0 = *(const uint4*)(ArH + kb);       rah1 = *(const uint4*)(ArH + kb + 8);
            ral0 = *(const uint4*)(ArL + kb);       ral1 = *(const uint4*)(ArL + kb + 8);
            rbh0 = *(const uint4*)(BrH + bkb);      rbh1 = *(const uint4*)(BrH + bkb + 8);
            rbl0 = *(const uint4*)(BrL + bkb);      rbl1 = *(const uint4*)(BrL + bkb + 8);
        }

        const uint32_t aAH = sAH + buf * 10240, aAL = sAL + buf * 10240;
        const uint32_t aBH = sBH + buf * 8704,  aBL = sBL + buf * 8704;
#pragma unroll
        for (int ks = 0; ks < 2; ks++) {
            const uint32_t bko = (uint32_t)(ks * 16 * 272);
            const uint32_t ako = (uint32_t)(ks * 32);
            uint32_t bh[8], bl[8];
            ldmBT(bh,     aBH + bko + b_off);
            ldmBT(bh + 4, aBH + bko + b_off + 32);
            ldmBT(bl,     aBL + bko + b_off);
            ldmBT(bl + 4, aBL + bko + b_off + 32);
#pragma unroll
            for (int mi = 0; mi < 4; mi++) {
                uint32_t ah[4], al[4];
                ldmA(ah, aAH + a_off + ako + mi * 16 * 80);
                ldmA(al, aAL + a_off + ako + mi * 16 * 80);
#pragma unroll
                for (int ni = 0; ni < 4; ni++) {
                    mma_bf16(acc[mi][ni], ah, bh + ni * 2);
                    mma_bf16(acc[mi][ni], ah, bl + ni * 2);
                    mma_bf16(acc[mi][ni], al, bh + ni * 2);
                }
            }
        }

        if (nxt) {
            const int nb = buf ^ 1;
            const uint32_t nAH = sAH + nb * 10240, nAL = sAL + nb * 10240;
            const uint32_t nBH = sBH + nb * 8704,  nBL = sBL + nb * 8704;
            sts128(nAH + a_sts, rah0); sts128(nAH + a_sts + 16, rah1);
            sts128(nAL + a_sts, ral0); sts128(nAL + a_sts + 16, ral1);
            sts128(nBH + b_sts, rbh0); sts128(nBH + b_sts + 16, rbh1);
            sts128(nBL + b_sts, rbl0); sts128(nBL + b_sts + 16, rbl1);
        }
        __syncthreads();
    }

    // ---- epilogue ----
#pragma unroll
    for (int mi = 0; mi < 4; mi++) {
        const int rbase = row0 + wm * 64 + mi * 16 + (lane >> 2);
#pragma unroll
        for (int ni = 0; ni < 4; ni++) {
            const int c = col0 + wn * 32 + ni * 8 + (lane & 3) * 2;
#pragma unroll
            for (int half = 0; half < 2; half++) {
                const int r = rbase + half * 8;
                float v0 = acc[mi][ni][2 * half + 0];
                float v1 = acc[mi][ni][2 * half + 1];
                if (EPI & 1) {
                    float2 b2 = *(const float2*)&bias[c];
                    v0 += b2.x; v1 += b2.y;
                }
                if (EPI & 2) {
                    const float cst = 0.70710678118654752f;
                    v0 = 0.5f * v0 * (1.0f + erff(v0 * cst));
                    v1 = 0.5f * v1 * (1.0f + erff(v1 * cst));
                }
                const size_t off = (size_t)r * Ncols + c;
                if (EPI & 8) {
                    uint32_t h, l;
                    split2(v0, v1, h, l);
                    *(uint32_t*)(Ch + off) = h;
                    *(uint32_t*)(Cl + off) = l;
                } else {
                    if (EPI & 4) {
                        float2 o = *(const float2*)&C[off];
                        v0 += o.x; v1 += o.y;
                    }
                    float2 w; w.x = v0; w.y = v1;
                    *(float2*)&C[off] = w;
                }
            }
        }
    }
}

// ---------------------------------------------------------------------------
// Weight prep: concat+split Wq|Wk|Wv, split W0/W1
// ---------------------------------------------------------------------------
__global__ void __launch_bounds__(256) prep_qkv(const float* __restrict__ Wq,
                                                const float* __restrict__ Wk,
                                                const float* __restrict__ Wv,
                                                const float* __restrict__ bq,
                                                const float* __restrict__ bk,
                                                const float* __restrict__ bv) {
    int idx = blockIdx.x * 256 + threadIdx.x;           // 768*2304
    int k = idx / QKVD, n = idx % QKVD;
    const float* src = (n < 768) ? Wq : (n < 1536) ? Wk : Wv;
    int nn = (n < 768) ? n : (n < 1536) ? n - 768 : n - 1536;
    bf16 h, l; split1(src[k * 768 + nn], h, l);
    g_wqkvh[idx] = h; g_wqkvl[idx] = l;
    if (idx < QKVD)
        g_bqkv[idx] = (idx < 768) ? bq[idx] : (idx < 1536) ? bk[idx - 768] : bv[idx - 1536];
}

__global__ void __launch_bounds__(256) prep_split(const float* __restrict__ W,
                                                  bf16* __restrict__ Wh,
                                                  bf16* __restrict__ Wl) {
    int idx = blockIdx.x * 256 + threadIdx.x;
    bf16 h, l; split1(W[idx], h, l);
    Wh[idx] = h; Wl[idx] = l;
}

// ---------------------------------------------------------------------------
// Block reduction + LayerNorm (writes split bf16 hi/lo)
// ---------------------------------------------------------------------------
__device__ __forceinline__ float blk_sum(float v) {
    __shared__ float red[8];
    int t = threadIdx.x;
#pragma unroll
    for (int o = 16; o; o >>= 1) v += __shfl_xor_sync(0xffffffffu, v, o);
    if ((t & 31) == 0) red[t >> 5] = v;
    __syncthreads();
    if (t < 32) {
        float w = (t < 8) ? red[t] : 0.f;
#pragma unroll
        for (int o = 4; o; o >>= 1) w += __shfl_xor_sync(0xffffffffu, w, o);
        if (t == 0) red[0] = w;
    }
    __syncthreads();
    float r = red[0];
    __syncthreads();
    return r;
}

__global__ void __launch_bounds__(256) ln_kernel(const float* __restrict__ x,
                                                 const float* __restrict__ g,
                                                 const float* __restrict__ be,
                                                 bf16* __restrict__ yh,
                                                 bf16* __restrict__ yl) {
    int row = blockIdx.x;
    int t   = threadIdx.x;
    const float* xr = x + (size_t)row * DMODEL;
    float v0 = xr[t], v1 = xr[t + 256], v2 = xr[t + 512];
    float mean = blk_sum(v0 + v1 + v2) * (1.0f / DMODEL);
    float d0 = v0 - mean, d1 = v1 - mean, d2 = v2 - mean;
    float var = blk_sum(d0 * d0 + d1 * d1 + d2 * d2) * (1.0f / DMODEL);
    float rs = rsqrtf(var + LN_EPS);
    float y0 = d0 * rs * g[t]       + be[t];
    float y1 = d1 * rs * g[t + 256] + be[t + 256];
    float y2 = d2 * rs * g[t + 512] + be[t + 512];
    bf16 h, l;
    size_t base = (size_t)row * DMODEL;
    split1(y0, h, l); yh[base + t]       = h; yl[base + t]       = l;
    split1(y1, h, l); yh[base + t + 256] = h; yl[base + t + 256] = l;
    split1(y2, h, l); yh[base + t + 512] = h; yl[base + t + 512] = l;
}

// ---------------------------------------------------------------------------
// Fused flash-style attention (qkv packed fp32, row stride QKVD)
// ---------------------------------------------------------------------------
__global__ void __launch_bounds__(256) attn_kernel(const float* __restrict__ qkv,
                                                   float* __restrict__ x) {
    __shared__ __align__(16) float Qs[64][68];
    __shared__ __align__(16) float Ks[64][68];
    __shared__ __align__(16) float Vs[64][68];
    __shared__ __align__(16) float Ps[64][68];

    const int bh = blockIdx.y;
    const int b = bh / HEADS, h = bh % HEADS;
    const int q0 = blockIdx.x * 64;
    const float* qb = qkv + (size_t)b * SEQ * QKVD + h * HDIM;
    const float* kb = qb + 768;
    const float* vb = qb + 1536;

    const int tid = threadIdx.x;
    const int tx = tid & 15, ty = tid >> 4;

    for (int i = tid; i < 64 * 16; i += 256) {
        int m = i >> 4, c = (i & 15) * 4;
        float4 t = *(const float4*)&qb[(size_t)(q0 + m) * QKVD + c];
        Qs[c + 0][m] = t.x; Qs[c + 1][m] = t.y;
        Qs[c + 2][m] = t.z; Qs[c + 3][m] = t.w;
    }

    float O[4][4] = {};
    float mrow[4], lrow[4];
#pragma unroll
    for (int i = 0; i < 4; i++) { mrow[i] = -1e30f; lrow[i] = 0.f; }

    for (int j0 = 0; j0 < SEQ; j0 += 64) {
        __syncthreads();
        for (int i = tid; i < 64 * 16; i += 256) {
            int m = i >> 4, c = (i & 15) * 4;
            float4 tk = *(const float4*)&kb[(size_t)(j0 + m) * QKVD + c];
            Ks[c + 0][m] = tk.x; Ks[c + 1][m] = tk.y;
            Ks[c + 2][m] = tk.z; Ks[c + 3][m] = tk.w;
            float4 tv = *(const float4*)&vb[(size_t)(j0 + m) * QKVD + c];
            Vs[m][c + 0] = tv.x; Vs[m][c + 1] = tv.y;
            Vs[m][c + 2] = tv.z; Vs[m][c + 3] = tv.w;
        }
        __syncthreads();

        float S[4][4] = {};
#pragma unroll 8
        for (int kk = 0; kk < 64; kk++) {
            float4 av = *(const float4*)&Qs[kk][ty * 4];
            float4 bv = *(const float4*)&Ks[kk][tx * 4];
            float a[4] = {av.x, av.y, av.z, av.w};
            float bb[4] = {bv.x, bv.y, bv.z, bv.w};
#pragma unroll
            for (int i = 0; i < 4; i++)
#pragma unroll
                for (int j = 0; j < 4; j++) S[i][j] = fmaf(a[i], bb[j], S[i][j]);
        }

        float scale[4], rsum[4];
#pragma unroll
        for (int i = 0; i < 4; i++) {
            float rmax = -1e30f;
#pragma unroll
            for (int j = 0; j < 4; j++) {
                S[i][j] *= 0.125f;
                rmax = fmaxf(rmax, S[i][j]);
            }
#pragma unroll
            for (int o = 8; o; o >>= 1)
                rmax = fmaxf(rmax, __shfl_xor_sync(0xffffffffu, rmax, o));
            float mnew = fmaxf(mrow[i], rmax);
            scale[i] = __expf(mrow[i] - mnew);
            mrow[i] = mnew;
            float rs = 0.f;
#pragma unroll
            for (int j = 0; j < 4; j++) {
                float p = __expf(S[i][j] - mnew);
                S[i][j] = p;
                rs += p;
            }
#pragma unroll
            for (int o = 8; o; o >>= 1)
                rs += __shfl_xor_sync(0xffffffffu, rs, o);
            rsum[i] = rs;
        }
#pragma unroll
        for (int i = 0; i < 4; i++) {
            lrow[i] = lrow[i] * scale[i] + rsum[i];
#pragma unroll
            for (int j = 0; j < 4; j++) {
                Ps[tx * 4 + j][ty * 4 + i] = S[i][j];
                O[i][j] *= scale[i];
            }
        }
        __syncthreads();

#pragma unroll 8
        for (int kk = 0; kk < 64; kk++) {
            float4 av = *(const float4*)&Ps[kk][ty * 4];
            float4 bv = *(const float4*)&Vs[kk][tx * 4];
            float a[4] = {av.x, av.y, av.z, av.w};
            float bb[4] = {bv.x, bv.y, bv.z, bv.w};
#pragma unroll
            for (int i = 0; i < 4; i++)
#pragma unroll
                for (int j = 0; j < 4; j++) O[i][j] = fmaf(a[i], bb[j], O[i][j]);
        }
    }

#pragma unroll
    for (int i = 0; i < 4; i++) {
        float inv = 1.0f / lrow[i];
        float* xr = x + (size_t)(b * SEQ + q0 + ty * 4 + i) * DMODEL + h * HDIM + tx * 4;
        float4 o4 = *(const float4*)xr;
        o4.x += O[i][0] * inv; o4.y += O[i][1] * inv;
        o4.z += O[i][2] * inv; o4.w += O[i][3] * inv;
        *(float4*)xr = o4;
    }
}

// ---------------------------------------------------------------------------
// Launch
// ---------------------------------------------------------------------------
extern "C" void kernel_launch(void* const* d_in, const int* in_sizes, int n_in,
                              void* d_out, int out_size) {
    const float* x  = (const float*)d_in[0];
    const float* Wq = (const float*)d_in[1];
    const float* bq = (const float*)d_in[2];
    const float* Wk = (const float*)d_in[3];
    const float* bk = (const float*)d_in[4];
    const float* Wv = (const float*)d_in[5];
    const float* bv = (const float*)d_in[6];
    const float* g1 = (const float*)d_in[7];
    const float* be1= (const float*)d_in[8];
    const float* g2 = (const float*)d_in[9];
    const float* be2= (const float*)d_in[10];
    const float* W0 = (const float*)d_in[11];
    const float* b0 = (const float*)d_in[12];
    const float* W1 = (const float*)d_in[13];
    const float* b1 = (const float*)d_in[14];
    float* out = (float*)d_out;

    bf16 *lnh, *lnl, *h1h, *h1l, *wqh, *wql, *w0h, *w0l, *w1h, *w1l;
    float *qkv, *bqkv;
    cudaGetSymbolAddress((void**)&lnh,  g_lnh);
    cudaGetSymbolAddress((void**)&lnl,  g_lnl);
    cudaGetSymbolAddress((void**)&h1h,  g_h1h);
    cudaGetSymbolAddress((void**)&h1l,  g_h1l);
    cudaGetSymbolAddress((void**)&wqh,  g_wqkvh);
    cudaGetSymbolAddress((void**)&wql,  g_wqkvl);
    cudaGetSymbolAddress((void**)&w0h,  g_w0h);
    cudaGetSymbolAddress((void**)&w0l,  g_w0l);
    cudaGetSymbolAddress((void**)&w1h,  g_w1h);
    cudaGetSymbolAddress((void**)&w1l,  g_w1l);
    cudaGetSymbolAddress((void**)&qkv,  g_qkv);
    cudaGetSymbolAddress((void**)&bqkv, g_bqkv);

    const int SMB = 75776;
    cudaFuncSetAttribute(hmma_gemm<1>,  cudaFuncAttributeMaxDynamicSharedMemorySize, SMB);
    cudaFuncSetAttribute(hmma_gemm<11>, cudaFuncAttributeMaxDynamicSharedMemorySize, SMB);
    cudaFuncSetAttribute(hmma_gemm<5>,  cudaFuncAttributeMaxDynamicSharedMemorySize, SMB);

    // residual stream lives in d_out; re-init every call for replay determinism
    cudaMemcpyAsync(out, x, sizeof(float) * (size_t)MROWS * DMODEL, cudaMemcpyDeviceToDevice);
    prep_qkv<<<(DMODEL * QKVD) / 256, 256>>>(Wq, Wk, Wv, bq, bk, bv);
    prep_split<<<(DMODEL * FFN) / 256, 256>>>(W0, w0h, w0l);
    prep_split<<<(FFN * DMODEL) / 256, 256>>>(W1, w1h, w1l);

    for (int blk = 0; blk < NBLK; blk++) {
        // --- attention sub-block ---
        ln_kernel<<<MROWS, 256>>>(out, g1, be1, lnh, lnl);
        hmma_gemm<1><<<dim3(QKVD / 128, MROWS / 128), 256, SMB>>>(
            lnh, lnl, wqh, wql, bqkv, qkv, nullptr, nullptr, QKVD, DMODEL);
        attn_kernel<<<dim3(SEQ / 64, BATCH * HEADS), 256>>>(qkv, out);   // out += attn

        // --- MLP sub-block ---
        ln_kernel<<<MROWS, 256>>>(out, g2, be2, lnh, lnl);
        hmma_gemm<11><<<dim3(FFN / 128, MROWS / 128), 256, SMB>>>(
            lnh, lnl, w0h, w0l, b0, nullptr, h1h, h1l, FFN, DMODEL);      // bias+gelu+split
        hmma_gemm<5><<<dim3(DMODEL / 128, MROWS / 128), 256, SMB>>>(
            h1h, h1l, w1h, w1l, b1, out, nullptr, nullptr, DMODEL, FFN);  // bias+residual
    }
}

// round 15
// speedup vs baseline: 2.5458x; 1.0877x over previous
#include <cuda_runtime.h>
#include <cuda_bf16.h>
#include <math.h>
#include <stdint.h>
#include <stddef.h>

// ---------------------------------------------------------------------------
// Transformer encoder, 12 blocks, shared weights.
// GEMMs: HMMA bf16 split precision, pre-split operands (R12: 5179 us).
// Fused flash attention on HMMA split-bf16 (reuses GEMM fragment maps).
// tcgen05 unusable: harness PTX targets sm_103 (no 'a').
// ---------------------------------------------------------------------------

#define BATCH   4
#define SEQ     512
#define DMODEL  768
#define QKVD    2304
#define FFN     3072
#define HEADS   12
#define HDIM    64
#define MROWS   2048
#define NBLK    12
#define LN_EPS  1e-5f

typedef __nv_bfloat16 bf16;

// Scratch (static device globals -- no allocations anywhere)
__device__ bf16  g_lnh [(size_t)MROWS * DMODEL];
__device__ bf16  g_lnl [(size_t)MROWS * DMODEL];
__device__ bf16  g_h1h [(size_t)MROWS * FFN];
__device__ bf16  g_h1l [(size_t)MROWS * FFN];
__device__ bf16  g_wqkvh[(size_t)DMODEL * QKVD];
__device__ bf16  g_wqkvl[(size_t)DMODEL * QKVD];
__device__ bf16  g_w0h [(size_t)DMODEL * FFN];
__device__ bf16  g_w0l [(size_t)DMODEL * FFN];
__device__ bf16  g_w1h [(size_t)FFN * DMODEL];
__device__ bf16  g_w1l [(size_t)FFN * DMODEL];
__device__ float g_qkv [(size_t)MROWS * QKVD];
__device__ float g_bqkv[QKVD];

// ---------------------------------------------------------------------------
// helpers
// ---------------------------------------------------------------------------
__device__ __forceinline__ uint32_t smem_u32(const void* p) {
    uint32_t a;
    asm("{ .reg .u64 t; cvta.to.shared.u64 t, %1; cvt.u32.u64 %0, t; }" : "=r"(a) : "l"(p));
    return a;
}
__device__ __forceinline__ void split2(float a, float b, uint32_t& h, uint32_t& l) {
    __nv_bfloat16 ha = __float2bfloat16_rn(a);
    __nv_bfloat16 hb = __float2bfloat16_rn(b);
    __nv_bfloat16 la = __float2bfloat16_rn(a - __bfloat162float(ha));
    __nv_bfloat16 lb = __float2bfloat16_rn(b - __bfloat162float(hb));
    h = ((uint32_t)__bfloat16_as_ushort(hb) << 16) | __bfloat16_as_ushort(ha);
    l = ((uint32_t)__bfloat16_as_ushort(lb) << 16) | __bfloat16_as_ushort(la);
}
__device__ __forceinline__ void split1(float a, bf16& h, bf16& l) {
    h = __float2bfloat16_rn(a);
    l = __float2bfloat16_rn(a - __bfloat162float(h));
}
__device__ __forceinline__ void sts128(uint32_t a, uint4 v) {
    asm volatile("st.shared.v4.b32 [%0], {%1,%2,%3,%4};"
        :: "r"(a), "r"(v.x), "r"(v.y), "r"(v.z), "r"(v.w) : "memory");
}
__device__ __forceinline__ void sts64(uint32_t a, uint32_t x, uint32_t y) {
    asm volatile("st.shared.v2.b32 [%0], {%1,%2};" :: "r"(a), "r"(x), "r"(y) : "memory");
}
__device__ __forceinline__ void sts32(uint32_t a, uint32_t v) {
    asm volatile("st.shared.b32 [%0], %1;" :: "r"(a), "r"(v) : "memory");
}
__device__ __forceinline__ void sts16(uint32_t a, uint16_t v) {
    asm volatile("st.shared.u16 [%0], %1;" :: "r"(a), "h"(v) : "memory");
}
__device__ __forceinline__ void sts_f2(uint32_t a, float x, float y) {
    asm volatile("st.shared.v2.f32 [%0], {%1,%2};" :: "r"(a), "f"(x), "f"(y) : "memory");
}
__device__ __forceinline__ void sts_f1(uint32_t a, float x) {
    asm volatile("st.shared.f32 [%0], %1;" :: "r"(a), "f"(x) : "memory");
}
__device__ __forceinline__ float lds_f(uint32_t a) {
    float v; asm volatile("ld.shared.f32 %0, [%1];" : "=f"(v) : "r"(a)); return v;
}
__device__ __forceinline__ float4 lds_f4(uint32_t a) {
    float4 v;
    asm volatile("ld.shared.v4.f32 {%0,%1,%2,%3}, [%4];"
        : "=f"(v.x), "=f"(v.y), "=f"(v.z), "=f"(v.w) : "r"(a));
    return v;
}
__device__ __forceinline__ void ldmA(uint32_t* r, uint32_t addr) {
    asm volatile("ldmatrix.sync.aligned.m8n8.x4.shared.b16 {%0,%1,%2,%3}, [%4];"
        : "=r"(r[0]), "=r"(r[1]), "=r"(r[2]), "=r"(r[3]) : "r"(addr));
}
__device__ __forceinline__ void ldmBT(uint32_t* r, uint32_t addr) {
    asm volatile("ldmatrix.sync.aligned.m8n8.x4.trans.shared.b16 {%0,%1,%2,%3}, [%4];"
        : "=r"(r[0]), "=r"(r[1]), "=r"(r[2]), "=r"(r[3]) : "r"(addr));
}
__device__ __forceinline__ void mma_bf16(float* c, const uint32_t* a, const uint32_t* b) {
    asm volatile("mma.sync.aligned.m16n8k16.row.col.f32.bf16.bf16.f32 "
        "{%0,%1,%2,%3}, {%4,%5,%6,%7}, {%8,%9}, {%0,%1,%2,%3};"
        : "+f"(c[0]), "+f"(c[1]), "+f"(c[2]), "+f"(c[3])
        : "r"(a[0]), "r"(a[1]), "r"(a[2]), "r"(a[3]), "r"(b[0]), "r"(b[1]));
}

// ---------------------------------------------------------------------------
// HMMA GEMM, pre-split operands (unchanged from R12 passing kernel)
// ---------------------------------------------------------------------------
template <int EPI>
__global__ void __launch_bounds__(256) hmma_gemm(const bf16* __restrict__ Ah,
                                                 const bf16* __restrict__ Al,
                                                 const bf16* __restrict__ Bh,
                                                 const bf16* __restrict__ Bl,
                                                 const float* __restrict__ bias,
                                                 float* __restrict__ C,
                                                 bf16* __restrict__ Ch,
                                                 bf16* __restrict__ Cl,
                                                 int Ncols, int Kdim) {
    extern __shared__ char smem[];
    const uint32_t sb  = smem_u32(smem);
    const uint32_t sAH = sb, sAL = sb + 20480, sBH = sb + 40960, sBL = sb + 58368;

    const int tid = threadIdx.x, lane = tid & 31, wid = tid >> 5;
    const int wm = wid & 1, wn = wid >> 1;
    const int row0 = blockIdx.y * 128, col0 = blockIdx.x * 128;

    const int arow = tid >> 1, aseg = tid & 1;
    const int bkrow = tid >> 3, bseg = tid & 7;

    const bf16* ArH = Ah + (size_t)(row0 + arow) * Kdim + aseg * 16;
    const bf16* ArL = Al + (size_t)(row0 + arow) * Kdim + aseg * 16;
    const bf16* BrH = Bh + (size_t)bkrow * Ncols + col0 + bseg * 16;
    const bf16* BrL = Bl + (size_t)bkrow * Ncols + col0 + bseg * 16;
    const uint32_t a_sts = (uint32_t)(arow * 80 + aseg * 32);
    const uint32_t b_sts = (uint32_t)(bkrow * 272 + bseg * 32);

    const uint32_t a_off = (uint32_t)((wm * 64 + (lane & 15)) * 80 + (lane >> 4) * 16);
    const uint32_t b_off = (uint32_t)((lane & 15) * 272 + (wn * 32 + (lane >> 4) * 8) * 2);

    float acc[4][4][4];
#pragma unroll
    for (int i = 0; i < 4; i++)
#pragma unroll
        for (int j = 0; j < 4; j++)
#pragma unroll
            for (int q = 0; q < 4; q++) acc[i][j][q] = 0.f;

    const int KT = Kdim / 32;
    uint4 rah0, rah1, ral0, ral1, rbh0, rbh1, rbl0, rbl1;

    rah0 = *(const uint4*)(ArH);     rah1 = *(const uint4*)(ArH + 8);
    ral0 = *(const uint4*)(ArL);     ral1 = *(const uint4*)(ArL + 8);
    rbh0 = *(const uint4*)(BrH);     rbh1 = *(const uint4*)(BrH + 8);
    rbl0 = *(const uint4*)(BrL);     rbl1 = *(const uint4*)(BrL + 8);
    sts128(sAH + a_sts, rah0); sts128(sAH + a_sts + 16, rah1);
    sts128(sAL + a_sts, ral0); sts128(sAL + a_sts + 16, ral1);
    sts128(sBH + b_sts, rbh0); sts128(sBH + b_sts + 16, rbh1);
    sts128(sBL + b_sts, rbl0); sts128(sBL + b_sts + 16, rbl1);
    __syncthreads();

    for (int st = 0; st < KT; st++) {
        const int buf = st & 1;
        const bool nxt = (st + 1 < KT);

        if (nxt) {
            const int kb = (st + 1) * 32;
            const size_t bkb = (size_t)kb * Ncols;
            rah0 = *(const uint4*)(ArH + kb);       rah1 = *(const uint4*)(ArH + kb + 8);
            ral0 = *(const uint4*)(ArL + kb);       ral1 = *(const uint4*)(ArL + kb + 8);
            rbh0 = *(const uint4*)(BrH + bkb);      rbh1 = *(const uint4*)(BrH + bkb + 8);
            rbl0 = *(const uint4*)(BrL + bkb);      rbl1 = *(const uint4*)(BrL + bkb + 8);
        }

        const uint32_t aAH = sAH + buf * 10240, aAL = sAL + buf * 10240;
        const uint32_t aBH = sBH + buf * 8704,  aBL = sBL + buf * 8704;
#pragma unroll
        for (int ks = 0; ks < 2; ks++) {
            const uint32_t bko = (uint32_t)(ks * 16 * 272);
            const uint32_t ako = (uint32_t)(ks * 32);
            uint32_t bh[8], bl[8];
            ldmBT(bh,     aBH + bko + b_off);
            ldmBT(bh + 4, aBH + bko + b_off + 32);
            ldmBT(bl,     aBL + bko + b_off);
            ldmBT(bl + 4, aBL + bko + b_off + 32);
#pragma unroll
            for (int mi = 0; mi < 4; mi++) {
                uint32_t ah[4], al[4];
                ldmA(ah, aAH + a_off + ako + mi * 16 * 80);
                ldmA(al, aAL + a_off + ako + mi * 16 * 80);
#pragma unroll
                for (int ni = 0; ni < 4; ni++) {
                    mma_bf16(acc[mi][ni], ah, bh + ni * 2);
                    mma_bf16(acc[mi][ni], ah, bl + ni * 2);
                    mma_bf16(acc[mi][ni], al, bh + ni * 2);
                }
            }
        }

        if (nxt) {
            const int nb = buf ^ 1;
            const uint32_t nAH = sAH + nb * 10240, nAL = sAL + nb * 10240;
            const uint32_t nBH = sBH + nb * 8704,  nBL = sBL + nb * 8704;
            sts128(nAH + a_sts, rah0); sts128(nAH + a_sts + 16, rah1);
            sts128(nAL + a_sts, ral0); sts128(nAL + a_sts + 16, ral1);
            sts128(nBH + b_sts, rbh0); sts128(nBH + b_sts + 16, rbh1);
            sts128(nBL + b_sts, rbl0); sts128(nBL + b_sts + 16, rbl1);
        }
        __syncthreads();
    }

#pragma unroll
    for (int mi = 0; mi < 4; mi++) {
        const int rbase = row0 + wm * 64 + mi * 16 + (lane >> 2);
#pragma unroll
        for (int ni = 0; ni < 4; ni++) {
            const int c = col0 + wn * 32 + ni * 8 + (lane & 3) * 2;
#pragma unroll
            for (int half = 0; half < 2; half++) {
                const int r = rbase + half * 8;
                float v0 = acc[mi][ni][2 * half + 0];
                float v1 = acc[mi][ni][2 * half + 1];
                if (EPI & 1) {
                    float2 b2 = *(const float2*)&bias[c];
                    v0 += b2.x; v1 += b2.y;
                }
                if (EPI & 2) {
                    const float cst = 0.70710678118654752f;
                    v0 = 0.5f * v0 * (1.0f + erff(v0 * cst));
                    v1 = 0.5f * v1 * (1.0f + erff(v1 * cst));
                }
                const size_t off = (size_t)r * Ncols + c;
                if (EPI & 8) {
                    uint32_t h, l;
                    split2(v0, v1, h, l);
                    *(uint32_t*)(Ch + off) = h;
                    *(uint32_t*)(Cl + off) = l;
                } else {
                    if (EPI & 4) {
                        float2 o = *(const float2*)&C[off];
                        v0 += o.x; v1 += o.y;
                    }
                    float2 w; w.x = v0; w.y = v1;
                    *(float2*)&C[off] = w;
                }
            }
        }
    }
}

// ---------------------------------------------------------------------------
// Weight prep
// ---------------------------------------------------------------------------
__global__ void __launch_bounds__(256) prep_qkv(const float* __restrict__ Wq,
                                                const float* __restrict__ Wk,
                                                const float* __restrict__ Wv,
                                                const float* __restrict__ bq,
                                                const float* __restrict__ bk,
                                                const float* __restrict__ bv) {
    int idx = blockIdx.x * 256 + threadIdx.x;
    int k = idx / QKVD, n = idx % QKVD;
    const float* src = (n < 768) ? Wq : (n < 1536) ? Wk : Wv;
    int nn = (n < 768) ? n : (n < 1536) ? n - 768 : n - 1536;
    bf16 h, l; split1(src[k * 768 + nn], h, l);
    g_wqkvh[idx] = h; g_wqkvl[idx] = l;
    if (idx < QKVD)
        g_bqkv[idx] = (idx < 768) ? bq[idx] : (idx < 1536) ? bk[idx - 768] : bv[idx - 1536];
}

__global__ void __launch_bounds__(256) prep_split(const float* __restrict__ W,
                                                  bf16* __restrict__ Wh,
                                                  bf16* __restrict__ Wl) {
    int idx = blockIdx.x * 256 + threadIdx.x;
    bf16 h, l; split1(W[idx], h, l);
    Wh[idx] = h; Wl[idx] = l;
}

// ---------------------------------------------------------------------------
// Block reduction + LayerNorm (unchanged)
// ---------------------------------------------------------------------------
__device__ __forceinline__ float blk_sum(float v) {
    __shared__ float red[8];
    int t = threadIdx.x;
#pragma unroll
    for (int o = 16; o; o >>= 1) v += __shfl_xor_sync(0xffffffffu, v, o);
    if ((t & 31) == 0) red[t >> 5] = v;
    __syncthreads();
    if (t < 32) {
        float w = (t < 8) ? red[t] : 0.f;
#pragma unroll
        for (int o = 4; o; o >>= 1) w += __shfl_xor_sync(0xffffffffu, w, o);
        if (t == 0) red[0] = w;
    }
    __syncthreads();
    float r = red[0];
    __syncthreads();
    return r;
}

__global__ void __launch_bounds__(256) ln_kernel(const float* __restrict__ x,
                                                 const float* __restrict__ g,
                                                 const float* __restrict__ be,
                                                 bf16* __restrict__ yh,
                                                 bf16* __restrict__ yl) {
    int row = blockIdx.x;
    int t   = threadIdx.x;
    const float* xr = x + (size_t)row * DMODEL;
    float v0 = xr[t], v1 = xr[t + 256], v2 = xr[t + 512];
    float mean = blk_sum(v0 + v1 + v2) * (1.0f / DMODEL);
    float d0 = v0 - mean, d1 = v1 - mean, d2 = v2 - mean;
    float var = blk_sum(d0 * d0 + d1 * d1 + d2 * d2) * (1.0f / DMODEL);
    float rs = rsqrtf(var + LN_EPS);
    float y0 = d0 * rs * g[t]       + be[t];
    float y1 = d1 * rs * g[t + 256] + be[t + 256];
    float y2 = d2 * rs * g[t + 512] + be[t + 512];
    bf16 h, l;
    size_t base = (size_t)row * DMODEL;
    split1(y0, h, l); yh[base + t]       = h; yl[base + t]       = l;
    split1(y1, h, l); yh[base + t + 256] = h; yl[base + t + 256] = l;
    split1(y2, h, l); yh[base + t + 512] = h; yl[base + t + 512] = l;
}

// ---------------------------------------------------------------------------
// Fused flash attention on HMMA, split-bf16 3-term.
// One CTA = 64 queries x one (b,h). 8 warps: mi2 = wid&3 (16 rows),
// wn = wid>>2 (32 cols). Per 64-key slab: S = QK^T (mma) -> smem fp32 ->
// SIMT online softmax -> split-bf16 P -> O rescale -> O += P.V (mma).
// smem tiles: bf16 [64][72] stride 144B; S fp32 [64][68] stride 272B.
// ---------------------------------------------------------------------------
#define ASA 144
#define ASS 272

__global__ void __launch_bounds__(256) attn_kernel(const float* __restrict__ qkv,
                                                   float* __restrict__ x) {
    extern __shared__ char smem[];
    const uint32_t sb = smem_u32(smem);
    const uint32_t QH = sb,          QL = sb + 9216;
    const uint32_t KH = sb + 18432,  KL = sb + 27648;
    const uint32_t VH = sb + 36864,  VL = sb + 46080;
    const uint32_t PH = sb + 55296,  PL = sb + 64512;
    const uint32_t SQ = sb + 73728;                  // fp32 scores 64x68
    const uint32_t SM = sb + 91136, SL = sb + 91392, SC = sb + 91648;

    const int bh = blockIdx.y;
    const int b = bh / HEADS, h = bh % HEADS;
    const int q0 = blockIdx.x * 64;
    const float* qb = qkv + (size_t)b * SEQ * QKVD + h * HDIM;
    const float* kb = qb + 768;
    const float* vb = qb + 1536;

    const int tid = threadIdx.x, lane = tid & 31, wid = tid >> 5;
    const int mi2 = wid & 3, wn = wid >> 2;
    const uint32_t a_off = (uint32_t)((mi2 * 16 + (lane & 15)) * ASA + (lane >> 4) * 16);
    const uint32_t b_off = (uint32_t)((lane & 15) * ASA + (wn * 32 + (lane >> 4) * 8) * 2);
    const int r0 = mi2 * 16 + (lane >> 2);           // fragment row (second = r0+8)

    // --- load Q tile (split bf16, row-major [q][hd]) + init stats ---
    {
        int qr = tid >> 2, c0 = (tid & 3) * 16;
        const float* src = qb + (size_t)(q0 + qr) * QKVD + c0;
        uint32_t dh = QH + qr * ASA + c0 * 2;
        uint32_t dl = QL + qr * ASA + c0 * 2;
#pragma unroll
        for (int j4 = 0; j4 < 4; j4++) {
            float4 t = *(const float4*)(src + j4 * 4);
            uint32_t h0, l0, h1, l1;
            split2(t.x, t.y, h0, l0);
            split2(t.z, t.w, h1, l1);
            sts64(dh + j4 * 8, h0, h1);
            sts64(dl + j4 * 8, l0, l1);
        }
        if (tid < 64) { sts_f1(SM + tid * 4, -1e30f); sts_f1(SL + tid * 4, 0.f); }
    }

    float oacc[4][4];
#pragma unroll
    for (int i = 0; i < 4; i++)
#pragma unroll
        for (int j = 0; j < 4; j++) oacc[i][j] = 0.f;

    for (int j0 = 0; j0 < SEQ; j0 += 64) {
        __syncthreads();   // prior slab's PV reads of K/V/P done

        // --- load K (transposed -> [hd][key]) and V ([key][hd]), split ---
        {
            int kr = tid >> 2, c0 = (tid & 3) * 16;
            const float* ksrc = kb + (size_t)(j0 + kr) * QKVD + c0;
            const float* vsrc = vb + (size_t)(j0 + kr) * QKVD + c0;
            uint32_t vdh = VH + kr * ASA + c0 * 2;
            uint32_t vdl = VL + kr * ASA + c0 * 2;
#pragma unroll
            for (int j4 = 0; j4 < 4; j4++) {
                float4 t = *(const float4*)(ksrc + j4 * 4);
                bf16 hh, ll;
                int c = c0 + j4 * 4;
                split1(t.x, hh, ll);
                sts16(KH + (c + 0) * ASA + kr * 2, __bfloat16_as_ushort(hh));
                sts16(KL + (c + 0) * ASA + kr * 2, __bfloat16_as_ushort(ll));
                split1(t.y, hh, ll);
                sts16(KH + (c + 1) * ASA + kr * 2, __bfloat16_as_ushort(hh));
                sts16(KL + (c + 1) * ASA + kr * 2, __bfloat16_as_ushort(ll));
                split1(t.z, hh, ll);
                sts16(KH + (c + 2) * ASA + kr * 2, __bfloat16_as_ushort(hh));
                sts16(KL + (c + 2) * ASA + kr * 2, __bfloat16_as_ushort(ll));
                split1(t.w, hh, ll);
                sts16(KH + (c + 3) * ASA + kr * 2, __bfloat16_as_ushort(hh));
                sts16(KL + (c + 3) * ASA + kr * 2, __bfloat16_as_ushort(ll));

                float4 u = *(const float4*)(vsrc + j4 * 4);
                uint32_t h0, l0, h1, l1;
                split2(u.x, u.y, h0, l0);
                split2(u.z, u.w, h1, l1);
                sts64(vdh + j4 * 8, h0, h1);
                sts64(vdl + j4 * 8, l0, l1);
            }
        }
        __syncthreads();

        // --- S = Q K^T (3-term split), fragments -> smem fp32 ---
        {
            float sacc[4][4];
#pragma unroll
            for (int i = 0; i < 4; i++)
#pragma unroll
                for (int j = 0; j < 4; j++) sacc[i][j] = 0.f;
#pragma unroll
            for (int ks = 0; ks < 4; ks++) {
                const uint32_t bko = (uint32_t)(ks * 16 * ASA);
                uint32_t bhf[8], blf[8];
                ldmBT(bhf,     KH + bko + b_off);
                ldmBT(bhf + 4, KH + bko + b_off + 32);
                ldmBT(blf,     KL + bko + b_off);
                ldmBT(blf + 4, KL + bko + b_off + 32);
                uint32_t ah[4], al[4];
                ldmA(ah, QH + a_off + ks * 32);
                ldmA(al, QL + a_off + ks * 32);
#pragma unroll
                for (int ni = 0; ni < 4; ni++) {
                    mma_bf16(sacc[ni], ah, bhf + ni * 2);
                    mma_bf16(sacc[ni], ah, blf + ni * 2);
                    mma_bf16(sacc[ni], al, bhf + ni * 2);
                }
            }
#pragma unroll
            for (int ni = 0; ni < 4; ni++) {
                int col = wn * 32 + ni * 8 + (lane & 3) * 2;
                sts_f2(SQ + r0 * ASS + col * 4,       sacc[ni][0], sacc[ni][1]);
                sts_f2(SQ + (r0 + 8) * ASS + col * 4, sacc[ni][2], sacc[ni][3]);
            }
        }
        __syncthreads();

        // --- online softmax (4 threads per row), write split-bf16 P ---
        {
            int row = tid >> 2, seg = tid & 3;
            uint32_t srow = SQ + row * ASS + seg * 64;
            float s[16];
#pragma unroll
            for (int j4 = 0; j4 < 4; j4++) {
                float4 t = lds_f4(srow + j4 * 16);
                s[j4 * 4 + 0] = t.x * 0.125f; s[j4 * 4 + 1] = t.y * 0.125f;
                s[j4 * 4 + 2] = t.z * 0.125f; s[j4 * 4 + 3] = t.w * 0.125f;
            }
            float m_old = lds_f(SM + row * 4);
            float l_old = lds_f(SL + row * 4);
            float rmax = -1e30f;
#pragma unroll
            for (int j = 0; j < 16; j++) rmax = fmaxf(rmax, s[j]);
            rmax = fmaxf(rmax, __shfl_xor_sync(0xffffffffu, rmax, 1));
            rmax = fmaxf(rmax, __shfl_xor_sync(0xffffffffu, rmax, 2));
            float mnew = fmaxf(m_old, rmax);
            float scf  = __expf(m_old - mnew);
            float rs = 0.f;
#pragma unroll
            for (int j = 0; j < 16; j++) { s[j] = __expf(s[j] - mnew); rs += s[j]; }
            rs += __shfl_xor_sync(0xffffffffu, rs, 1);
            rs += __shfl_xor_sync(0xffffffffu, rs, 2);
            if (seg == 0) {
                sts_f1(SM + row * 4, mnew);
                sts_f1(SL + row * 4, l_old * scf + rs);
                sts_f1(SC + row * 4, scf);
            }
            uint32_t pdh = PH + row * ASA + (seg * 16) * 2;
            uint32_t pdl = PL + row * ASA + (seg * 16) * 2;
#pragma unroll
            for (int j = 0; j < 8; j++) {
                uint32_t hh, ll;
                split2(s[2 * j], s[2 * j + 1], hh, ll);
                sts32(pdh + j * 4, hh);
                sts32(pdl + j * 4, ll);
            }
        }
        __syncthreads();

        // --- rescale O, then O += P.V (3-term split) ---
        {
            float s0 = lds_f(SC + r0 * 4);
            float s1 = lds_f(SC + (r0 + 8) * 4);
#pragma unroll
            for (int ni = 0; ni < 4; ni++) {
                oacc[ni][0] *= s0; oacc[ni][1] *= s0;
                oacc[ni][2] *= s1; oacc[ni][3] *= s1;
            }
#pragma unroll
            for (int ks = 0; ks < 4; ks++) {
                const uint32_t bko = (uint32_t)(ks * 16 * ASA);
                uint32_t bhf[8], blf[8];
                ldmBT(bhf,     VH + bko + b_off);
                ldmBT(bhf + 4, VH + bko + b_off + 32);
                ldmBT(blf,     VL + bko + b_off);
                ldmBT(blf + 4, VL + bko + b_off + 32);
                uint32_t ah[4], al[4];
                ldmA(ah, PH + a_off + ks * 32);
                ldmA(al, PL + a_off + ks * 32);
#pragma unroll
                for (int ni = 0; ni < 4; ni++) {
                    mma_bf16(oacc[ni], ah, bhf + ni * 2);
                    mma_bf16(oacc[ni], ah, blf + ni * 2);
                    mma_bf16(oacc[ni], al, bhf + ni * 2);
                }
            }
        }
    }

    // --- normalize + residual add ---
    {
        float inv0 = 1.0f / lds_f(SL + r0 * 4);
        float inv1 = 1.0f / lds_f(SL + (r0 + 8) * 4);
#pragma unroll
        for (int ni = 0; ni < 4; ni++) {
            int col = wn * 32 + ni * 8 + (lane & 3) * 2;
            float* x0 = x + (size_t)(b * SEQ + q0 + r0) * DMODEL + h * HDIM + col;
            float* x1 = x + (size_t)(b * SEQ + q0 + r0 + 8) * DMODEL + h * HDIM + col;
            float2 o0 = *(const float2*)x0;
            o0.x += oacc[ni][0] * inv0; o0.y += oacc[ni][1] * inv0;
            *(float2*)x0 = o0;
            float2 o1 = *(const float2*)x1;
            o1.x += oacc[ni][2] * inv1; o1.y += oacc[ni][3] * inv1;
            *(float2*)x1 = o1;
        }
    }
}

// ---------------------------------------------------------------------------
// Launch
// ---------------------------------------------------------------------------
extern "C" void kernel_launch(void* const* d_in, const int* in_sizes, int n_in,
                              void* d_out, int out_size) {
    const float* x  = (const float*)d_in[0];
    const float* Wq = (const float*)d_in[1];
    const float* bq = (const float*)d_in[2];
    const float* Wk = (const float*)d_in[3];
    const float* bk = (const float*)d_in[4];
    const float* Wv = (const float*)d_in[5];
    const float* bv = (const float*)d_in[6];
    const float* g1 = (const float*)d_in[7];
    const float* be1= (const float*)d_in[8];
    const float* g2 = (const float*)d_in[9];
    const float* be2= (const float*)d_in[10];
    const float* W0 = (const float*)d_in[11];
    const float* b0 = (const float*)d_in[12];
    const float* W1 = (const float*)d_in[13];
    const float* b1 = (const float*)d_in[14];
    float* out = (float*)d_out;

    bf16 *lnh, *lnl, *h1h, *h1l, *wqh, *wql, *w0h, *w0l, *w1h, *w1l;
    float *qkv, *bqkv;
    cudaGetSymbolAddress((void**)&lnh,  g_lnh);
    cudaGetSymbolAddress((void**)&lnl,  g_lnl);
    cudaGetSymbolAddress((void**)&h1h,  g_h1h);
    cudaGetSymbolAddress((void**)&h1l,  g_h1l);
    cudaGetSymbolAddress((void**)&wqh,  g_wqkvh);
    cudaGetSymbolAddress((void**)&wql,  g_wqkvl);
    cudaGetSymbolAddress((void**)&w0h,  g_w0h);
    cudaGetSymbolAddress((void**)&w0l,  g_w0l);
    cudaGetSymbolAddress((void**)&w1h,  g_w1h);
    cudaGetSymbolAddress((void**)&w1l,  g_w1l);
    cudaGetSymbolAddress((void**)&qkv,  g_qkv);
    cudaGetSymbolAddress((void**)&bqkv, g_bqkv);

    const int SMB  = 75776;
    const int SMA  = 92160;
    cudaFuncSetAttribute(hmma_gemm<1>,  cudaFuncAttributeMaxDynamicSharedMemorySize, SMB);
    cudaFuncSetAttribute(hmma_gemm<11>, cudaFuncAttributeMaxDynamicSharedMemorySize, SMB);
    cudaFuncSetAttribute(hmma_gemm<5>,  cudaFuncAttributeMaxDynamicSharedMemorySize, SMB);
    cudaFuncSetAttribute(attn_kernel,   cudaFuncAttributeMaxDynamicSharedMemorySize, SMA);

    // residual stream lives in d_out; re-init every call for replay determinism
    cudaMemcpyAsync(out, x, sizeof(float) * (size_t)MROWS * DMODEL, cudaMemcpyDeviceToDevice);
    prep_qkv<<<(DMODEL * QKVD) / 256, 256>>>(Wq, Wk, Wv, bq, bk, bv);
    prep_split<<<(DMODEL * FFN) / 256, 256>>>(W0, w0h, w0l);
    prep_split<<<(FFN * DMODEL) / 256, 256>>>(W1, w1h, w1l);

    for (int blk = 0; blk < NBLK; blk++) {
        // --- attention sub-block ---
        ln_kernel<<<MROWS, 256>>>(out, g1, be1, lnh, lnl);
        hmma_gemm<1><<<dim3(QKVD / 128, MROWS / 128), 256, SMB>>>(
            lnh, lnl, wqh, wql, bqkv, qkv, nullptr, nullptr, QKVD, DMODEL);
        attn_kernel<<<dim3(SEQ / 64, BATCH * HEADS), 256, SMA>>>(qkv, out);

        // --- MLP sub-block ---
        ln_kernel<<<MROWS, 256>>>(out, g2, be2, lnh, lnl);
        hmma_gemm<11><<<dim3(FFN / 128, MROWS / 128), 256, SMB>>>(
            lnh, lnl, w0h, w0l, b0, nullptr, h1h, h1l, FFN, DMODEL);
        hmma_gemm<5><<<dim3(DMODEL / 128, MROWS / 128), 256, SMB>>>(
            h1h, h1l, w1h, w1l, b1, out, nullptr, nullptr, DMODEL, FFN);
    }
}